// round 4
// baseline (speedup 1.0000x reference)
#include <cuda_runtime.h>
#include <math.h>

#define NT   1024  // 32 warps: thread = (o, q, h)
#define BSUB 8
#define TT   128
#define DD   256
#define HW   128
#define YS   12    // padded state stride

__device__ __forceinline__ float tanha(float x) {
    float y; asm("tanh.approx.f32 %0, %1;" : "=f"(y) : "f"(x)); return y;
}
#define FFMA2(acc, a, b) \
    asm("fma.rn.f32x2 %0, %1, %2, %3;" : "=l"(acc) : "l"(a), "l"(b), "l"(acc))
#define PACK2(d, lo, hi) \
    asm("mov.b64 %0, {%1,%2};" : "=l"(d) : "f"(lo), "f"(hi))
#define UNPACK2(lo, hi, d) \
    asm("mov.b64 {%0,%1}, %2;" : "=f"(lo), "=f"(hi) : "l"(d))

__device__ __forceinline__ float interp_c(float t, const float* __restrict__ row) {
    int i = (int)ceilf(t);
    i = i < 1 ? 1 : (i > DD - 1 ? DD - 1 : i);
    float w = t - (float)(i - 1);
    w = fminf(fmaxf(w, 0.f), 1.f);
    return (1.f - w) * row[i - 1] + w * row[i];
}

__global__ __launch_bounds__(NT, 1)
void ode_kernel(const float* __restrict__ ts, const float* __restrict__ y0,
                const float* __restrict__ latent, const int* __restrict__ length,
                const float* __restrict__ dts, const float* __restrict__ dcs,
                const float* __restrict__ W1, const float* __restrict__ b1,
                const float* __restrict__ W2, const float* __restrict__ b2,
                const float* __restrict__ W3, const float* __restrict__ b3,
                float* __restrict__ out)
{
    extern __shared__ float sm[];
    float* W3t    = sm;                 // [128][9]
    float* h1s    = W3t + 1152;         // [8][128]
    float* pS     = h1s + BSUB * HW;    // [4][8][128]
    float* bpre   = pS + 4 * BSUB * HW; // [8][128]
    float* csS    = bpre + BSUB * HW;   // [8][256]
    float* tsS    = csS + BSUB * DD;    // [128]
    float* b2s    = tsS + TT;           // [128]
    float* Ybase  = b2s + HW;           // [8][12]
    float* Ystage = Ybase + BSUB * YS;  // [8][12]
    float* Yacc   = Ystage + BSUB * YS; // [8][12]
    float* cS     = Yacc + BSUB * YS;   // [8]
    float* b3s    = cS + 8;             // [12]
    float* tendS  = b3s + 12;           // [8]

    const int tid = threadIdx.x;
    const int o   = tid & 127;
    const int qh  = tid >> 7;           // 0..7
    const int q   = qh & 3;             // k-quarter
    const int hh  = qh >> 2;            // row half
    const int r0  = blockIdx.x * BSUB;

    // ---- one-time setup ----
    for (int i = tid; i < 9 * HW; i += NT) {
        int oo = i >> 7, k = i & 127;
        W3t[k * 9 + oo] = W3[i];
    }
    for (int i = tid; i < BSUB * DD; i += NT) {
        int r = i >> 8;
        csS[i] = dcs[(r0 + r) * DD + (i & 255)];
    }
    if (tid < TT) tsS[tid] = ts[tid];
    if (tid >= 128 && tid < 256) b2s[tid - 128] = b2[tid - 128];
    if (tid >= 256 && tid < 265) b3s[tid - 256] = b3[tid - 256];
    if (tid >= 288 && tid < 296) {
        int r = tid - 288;
        int len = length[r0 + r];
        int idx = len - 1; if (idx < 0) idx = 0;
        tendS[r] = ts[idx];
        out[(r0 + r) * TT] = y0[r0 + r];
    }
    if (tid >= 320 && tid < 320 + BSUB * YS) {
        int i = tid - 320;
        int r = i / YS, j = i - r * YS;
        float v = (j == 0) ? y0[r0 + r] : 0.f;
        Ybase[i] = v;
        Yacc[i]  = v;
    }

    // ---- register-resident weights ----
    unsigned long long w2p[16];         // W2[o][32q .. 32q+31]
    {
        const float* wr = W2 + o * HW + 32 * q;
        #pragma unroll
        for (int j = 0; j < 16; ++j) PACK2(w2p[j], wr[2 * j], wr[2 * j + 1]);
    }
    unsigned long long w1p[5];
    float w1t, w1c;
    {
        const float* w = W1 + o * 43;
        PACK2(w1p[0], w[0], w[1]);
        PACK2(w1p[1], w[2], w[3]);
        PACK2(w1p[2], w[4], w[5]);
        PACK2(w1p[3], w[6], w[7]);
        PACK2(w1p[4], w[8], 0.f);
        w1t = w[41];
        w1c = w[42];
        // latent precompute for this thread's row (r = qh)
        float a = b1[o];
        const float* lat = latent + (r0 + qh) * 32;
        #pragma unroll
        for (int j = 0; j < 32; ++j) a += w[9 + j] * lat[j];
        bpre[qh * HW + o] = a;
    }
    __syncthreads();

    const float A[4]  = {0.f, 0.5f, 0.5f, 1.f};
    const float Wc[4] = {1.f, 2.f, 2.f, 1.f};
    const int wid = tid >> 5;
    const int l   = tid & 31;

    for (int n = 0; n < TT - 1; ++n) {
        float t0  = tsS[n];
        float dtf = (tsS[n + 1] - t0) * 0.5f;       // SUB = 2
        #pragma unroll 1
        for (int sub = 0; sub < 2; ++sub) {
            float tstart = t0 + (float)sub * dtf;
            if (tid < BSUB * YS) Ystage[tid] = Ybase[tid];
            if (tid >= 128 && tid < 128 + BSUB)
                cS[tid - 128] = interp_c(tstart, csS + (tid - 128) * DD);
            __syncthreads();

            #pragma unroll
            for (int s = 0; s < 4; ++s) {
                float tt  = tstart + A[s] * dtf;
                float wgt = dtf * (1.f / 6.f) * Wc[s];

                // ---- layer 1: one row per thread (row = qh) ----
                {
                    const int r = qh;
                    float base = bpre[r * HW + o] + w1t * tt + w1c * cS[r];
                    ulonglong2 ya = *reinterpret_cast<const ulonglong2*>(Ystage + r * YS);
                    ulonglong2 yb = *reinterpret_cast<const ulonglong2*>(Ystage + r * YS + 4);
                    unsigned long long y8p;
                    PACK2(y8p, Ystage[r * YS + 8], 0.f);
                    unsigned long long a2 = 0ull;
                    FFMA2(a2, w1p[0], ya.x);
                    FFMA2(a2, w1p[1], ya.y);
                    FFMA2(a2, w1p[2], yb.x);
                    FFMA2(a2, w1p[3], yb.y);
                    FFMA2(a2, w1p[4], y8p);
                    float lo, hi; UNPACK2(lo, hi, a2);
                    h1s[r * HW + o] = tanha(base + lo + hi);
                }
                __syncthreads();

                // ---- layer 2: 4 rows x 32 k per thread, W2 in regs ----
                {
                    unsigned long long acc[4] = {0ull, 0ull, 0ull, 0ull};
                    const float* hb = h1s + (hh * 4) * HW + 32 * q;
                    #pragma unroll
                    for (int j = 0; j < 8; ++j) {
                        #pragma unroll
                        for (int rr = 0; rr < 4; ++rr) {
                            ulonglong2 hv = *reinterpret_cast<const ulonglong2*>(hb + rr * HW + 4 * j);
                            FFMA2(acc[rr], w2p[2 * j],     hv.x);
                            FFMA2(acc[rr], w2p[2 * j + 1], hv.y);
                        }
                    }
                    float* pq = pS + q * (BSUB * HW) + (hh * 4) * HW + o;
                    #pragma unroll
                    for (int rr = 0; rr < 4; ++rr) {
                        float lo, hi; UNPACK2(lo, hi, acc[rr]);
                        pq[rr * HW] = lo + hi;
                    }
                }
                __syncthreads();

                // ---- layer 3: warp-per-row (warps 0-7), butterfly reduce ----
                if (wid < BSUB) {
                    const int r = wid;
                    float acc9[9];
                    #pragma unroll
                    for (int o2 = 0; o2 < 9; ++o2) acc9[o2] = 0.f;
                    const float* pr = pS + r * HW;
                    #pragma unroll
                    for (int j = 0; j < 4; ++j) {
                        int k = j * 32 + l;
                        float v = pr[k] + pr[1024 + k] + pr[2048 + k] + pr[3072 + k] + b2s[k];
                        float h = tanha(v);
                        #pragma unroll
                        for (int o2 = 0; o2 < 9; ++o2)
                            acc9[o2] += h * W3t[k * 9 + o2];
                    }
                    #pragma unroll
                    for (int off = 16; off > 0; off >>= 1) {
                        #pragma unroll
                        for (int o2 = 0; o2 < 9; ++o2)
                            acc9[o2] += __shfl_xor_sync(0xffffffffu, acc9[o2], off);
                    }
                    if (l < 9) {
                        float a = acc9[l] + b3s[l];
                        if (l == 0) a = -__cosf(a);
                        if (tt > tendS[r]) a = 0.f;
                        Yacc[r * YS + l] += wgt * a;
                        if (s < 3)
                            Ystage[r * YS + l] = Ybase[r * YS + l] + (A[s + 1] * dtf) * a;
                    }
                    if (l == 16 && s < 3)
                        cS[r] = interp_c(tstart + A[s + 1] * dtf, csS + r * DD);
                }
                __syncthreads();
            }

            if (tid < BSUB * YS) Ybase[tid] = Yacc[tid];
            __syncthreads();
        }
        if (tid < BSUB) out[(r0 + tid) * TT + n + 1] = Ybase[tid * YS];
    }
}

extern "C" void kernel_launch(void* const* d_in, const int* in_sizes, int n_in,
                              void* d_out, int out_size) {
    const float* ts     = (const float*)d_in[0];
    const float* y0     = (const float*)d_in[1];
    const float* latent = (const float*)d_in[2];
    const int*   length = (const int*)  d_in[3];
    const float* dts    = (const float*)d_in[4];
    const float* dcs    = (const float*)d_in[5];
    const float* W1     = (const float*)d_in[6];
    const float* b1     = (const float*)d_in[7];
    const float* W2     = (const float*)d_in[8];
    const float* b2     = (const float*)d_in[9];
    const float* W3     = (const float*)d_in[10];
    const float* b3     = (const float*)d_in[11];
    float* out = (float*)d_out;

    const size_t smem_floats = 1152 + BSUB * HW + 4 * BSUB * HW + BSUB * HW
                             + BSUB * DD + TT + HW + 3 * BSUB * YS + 8 + 12 + 8;
    const size_t smem = smem_floats * sizeof(float);   // ~39.7 KB
    cudaFuncSetAttribute(ode_kernel, cudaFuncAttributeMaxDynamicSharedMemorySize, (int)smem);

    ode_kernel<<<128, NT, smem>>>(ts, y0, latent, length, dts, dcs,
                                  W1, b1, W2, b2, W3, b3, out);
}

// round 5
// speedup vs baseline: 1.1297x; 1.1297x over previous
#include <cuda_runtime.h>
#include <math.h>

#define NT   256   // 8 warps; thread = (neuron o, k-half e)
#define BSUB 4     // batch rows per CTA
#define TT   128
#define DD   256
#define HW   128
#define YS   12    // padded state stride

__device__ __forceinline__ float tanha(float x) {
    float y; asm("tanh.approx.f32 %0, %1;" : "=f"(y) : "f"(x)); return y;
}
#define FFMA2(acc, a, b) \
    asm("fma.rn.f32x2 %0, %1, %2, %3;" : "=l"(acc) : "l"(a), "l"(b), "l"(acc))
#define PACK2(d, lo, hi) \
    asm("mov.b64 %0, {%1,%2};" : "=l"(d) : "f"(lo), "f"(hi))
#define UNPACK2(lo, hi, d) \
    asm("mov.b64 {%0,%1}, %2;" : "=f"(lo), "=f"(hi) : "l"(d))

__device__ __forceinline__ float interp_c(float t, const float* __restrict__ row) {
    int i = (int)ceilf(t);
    i = i < 1 ? 1 : (i > DD - 1 ? DD - 1 : i);
    float w = t - (float)(i - 1);
    w = fminf(fmaxf(w, 0.f), 1.f);
    return (1.f - w) * row[i - 1] + w * row[i];
}

__global__ __launch_bounds__(NT, 2)
void ode_kernel(const float* __restrict__ ts, const float* __restrict__ y0,
                const float* __restrict__ latent, const int* __restrict__ length,
                const float* __restrict__ dts, const float* __restrict__ dcs,
                const float* __restrict__ W1, const float* __restrict__ b1,
                const float* __restrict__ W2, const float* __restrict__ b2,
                const float* __restrict__ W3, const float* __restrict__ b3,
                float* __restrict__ out)
{
    extern __shared__ float sm[];
    float* W3t    = sm;                 // [128][9]
    float* h1s    = W3t + 1152;         // [4][128]
    float* pS     = h1s + BSUB * HW;    // [2][4][128]
    float* bpre   = pS + 2 * BSUB * HW; // [4][128]
    float* csS    = bpre + BSUB * HW;   // [4][256]
    float* tsS    = csS + BSUB * DD;    // [128]
    float* b2s    = tsS + TT;           // [128]
    float* Ybase  = b2s + HW;           // [4][12]
    float* Ystage = Ybase + BSUB * YS;  // [4][12]
    float* Yacc   = Ystage + BSUB * YS; // [4][12]
    float* cS     = Yacc + BSUB * YS;   // [4]
    float* b3s    = cS + 4;             // [12]
    float* tendS  = b3s + 12;           // [4]

    const int tid = threadIdx.x;
    const int o   = tid & 127;          // neuron
    const int e   = tid >> 7;           // k-half 0/1
    const int r0  = blockIdx.x * BSUB;

    // ---- one-time setup ----
    for (int i = tid; i < 9 * HW; i += NT) {
        int oo = i >> 7, k = i & 127;
        W3t[k * 9 + oo] = W3[i];
    }
    for (int i = tid; i < BSUB * DD; i += NT) {
        int r = i >> 8;
        csS[i] = dcs[(r0 + r) * DD + (i & 255)];
    }
    if (tid < TT) tsS[tid] = ts[tid];
    if (tid >= 128) b2s[tid - 128] = b2[tid - 128];
    if (tid < 9)  b3s[tid] = b3[tid];
    if (tid >= 16 && tid < 16 + BSUB) {
        int r = tid - 16;
        int len = length[r0 + r];
        int idx = len - 1; if (idx < 0) idx = 0;
        tendS[r] = ts[idx];
        out[(r0 + r) * TT] = y0[r0 + r];
    }
    if (tid >= 32 && tid < 32 + BSUB * YS) {
        int i = tid - 32;
        int r = i / YS, j = i - r * YS;
        float v = (j == 0) ? y0[r0 + r] : 0.f;
        Ybase[i] = v;
        Yacc[i]  = v;
    }

    // ---- register-resident weights ----
    unsigned long long w2p[32];         // W2[o][64e .. 64e+63]
    {
        const float* wr = W2 + o * HW + 64 * e;
        #pragma unroll
        for (int j = 0; j < 32; ++j) PACK2(w2p[j], wr[2 * j], wr[2 * j + 1]);
    }
    unsigned long long w1p[5];
    float w1t, w1c;
    {
        const float* w = W1 + o * 43;
        PACK2(w1p[0], w[0], w[1]);
        PACK2(w1p[1], w[2], w[3]);
        PACK2(w1p[2], w[4], w[5]);
        PACK2(w1p[3], w[6], w[7]);
        PACK2(w1p[4], w[8], 0.f);
        w1t = w[41];
        w1c = w[42];
        float bb = b1[o];
        #pragma unroll
        for (int rr = 0; rr < 2; ++rr) {    // rows 2e, 2e+1
            int r = 2 * e + rr;
            float a = bb;
            const float* lat = latent + (r0 + r) * 32;
            #pragma unroll
            for (int j = 0; j < 32; ++j) a += w[9 + j] * lat[j];
            bpre[r * HW + o] = a;
        }
    }
    __syncthreads();

    const float A[4]  = {0.f, 0.5f, 0.5f, 1.f};
    const float Wc[4] = {1.f, 2.f, 2.f, 1.f};
    const int wid = tid >> 5;           // warp 0..7
    const int l   = tid & 31;

    for (int n = 0; n < TT - 1; ++n) {
        float t0  = tsS[n];
        float dtf = (tsS[n + 1] - t0) * 0.5f;       // SUB = 2
        #pragma unroll 1
        for (int sub = 0; sub < 2; ++sub) {
            float tstart = t0 + (float)sub * dtf;
            if (tid < BSUB * YS) Ystage[tid] = Ybase[tid];
            if (tid >= 64 && tid < 64 + BSUB)
                cS[tid - 64] = interp_c(tstart, csS + (tid - 64) * DD);
            __syncthreads();

            #pragma unroll
            for (int s = 0; s < 4; ++s) {
                float tt  = tstart + A[s] * dtf;
                float wgt = dtf * (1.f / 6.f) * Wc[s];

                // ---- layer 1: thread (o,e) does rows 2e, 2e+1 ----
                #pragma unroll
                for (int rr = 0; rr < 2; ++rr) {
                    const int r = 2 * e + rr;
                    float base = bpre[r * HW + o] + w1t * tt + w1c * cS[r];
                    ulonglong2 ya = *reinterpret_cast<const ulonglong2*>(Ystage + r * YS);
                    ulonglong2 yb = *reinterpret_cast<const ulonglong2*>(Ystage + r * YS + 4);
                    unsigned long long y8p;
                    PACK2(y8p, Ystage[r * YS + 8], 0.f);
                    unsigned long long a2 = 0ull;
                    FFMA2(a2, w1p[0], ya.x);
                    FFMA2(a2, w1p[1], ya.y);
                    FFMA2(a2, w1p[2], yb.x);
                    FFMA2(a2, w1p[3], yb.y);
                    FFMA2(a2, w1p[4], y8p);
                    float lo, hi; UNPACK2(lo, hi, a2);
                    h1s[r * HW + o] = tanha(base + lo + hi);
                }
                __syncthreads();

                // ---- layer 2: 4 rows x 64 k per thread, W2 in regs ----
                {
                    unsigned long long acc[BSUB] = {0ull, 0ull, 0ull, 0ull};
                    const float* hb = h1s + 64 * e;
                    #pragma unroll 4
                    for (int j = 0; j < 16; ++j) {
                        #pragma unroll
                        for (int rr = 0; rr < BSUB; ++rr) {
                            ulonglong2 hv = *reinterpret_cast<const ulonglong2*>(hb + rr * HW + 4 * j);
                            FFMA2(acc[rr], w2p[2 * j],     hv.x);
                            FFMA2(acc[rr], w2p[2 * j + 1], hv.y);
                        }
                    }
                    float* pq = pS + e * (BSUB * HW) + o;
                    #pragma unroll
                    for (int rr = 0; rr < BSUB; ++rr) {
                        float lo, hi; UNPACK2(lo, hi, acc[rr]);
                        pq[rr * HW] = lo + hi;
                    }
                }
                __syncthreads();

                // ---- layer 3: warp-per-row (warps 0-3), butterfly reduce ----
                if (wid < BSUB) {
                    const int r = wid;
                    float acc9[9];
                    #pragma unroll
                    for (int o2 = 0; o2 < 9; ++o2) acc9[o2] = 0.f;
                    const float* pr = pS + r * HW;
                    #pragma unroll
                    for (int j = 0; j < 4; ++j) {
                        int k = j * 32 + l;
                        float v = pr[k] + pr[BSUB * HW + k] + b2s[k];
                        float h = tanha(v);
                        #pragma unroll
                        for (int o2 = 0; o2 < 9; ++o2)
                            acc9[o2] += h * W3t[k * 9 + o2];
                    }
                    #pragma unroll
                    for (int off = 16; off > 0; off >>= 1) {
                        #pragma unroll
                        for (int o2 = 0; o2 < 9; ++o2)
                            acc9[o2] += __shfl_xor_sync(0xffffffffu, acc9[o2], off);
                    }
                    if (l < 9) {
                        float a = acc9[l] + b3s[l];
                        if (l == 0) a = -__cosf(a);
                        if (tt > tendS[r]) a = 0.f;
                        Yacc[r * YS + l] += wgt * a;
                        if (s < 3)
                            Ystage[r * YS + l] = Ybase[r * YS + l] + (A[s + 1] * dtf) * a;
                    }
                    if (l == 16 && s < 3)
                        cS[r] = interp_c(tstart + A[s + 1] * dtf, csS + r * DD);
                }
                __syncthreads();
            }

            if (tid < BSUB * YS) Ybase[tid] = Yacc[tid];
            __syncthreads();
        }
        if (tid < BSUB) out[(r0 + tid) * TT + n + 1] = Ybase[tid * YS];
    }
}

extern "C" void kernel_launch(void* const* d_in, const int* in_sizes, int n_in,
                              void* d_out, int out_size) {
    const float* ts     = (const float*)d_in[0];
    const float* y0     = (const float*)d_in[1];
    const float* latent = (const float*)d_in[2];
    const int*   length = (const int*)  d_in[3];
    const float* dts    = (const float*)d_in[4];
    const float* dcs    = (const float*)d_in[5];
    const float* W1     = (const float*)d_in[6];
    const float* b1     = (const float*)d_in[7];
    const float* W2     = (const float*)d_in[8];
    const float* b2     = (const float*)d_in[9];
    const float* W3     = (const float*)d_in[10];
    const float* b3     = (const float*)d_in[11];
    float* out = (float*)d_out;

    const size_t smem_floats = 1152 + BSUB * HW + 2 * BSUB * HW + BSUB * HW
                             + BSUB * DD + TT + HW + 3 * BSUB * YS + 4 + 12 + 4;
    const size_t smem = smem_floats * sizeof(float);   // ~18.9 KB per CTA
    cudaFuncSetAttribute(ode_kernel, cudaFuncAttributeMaxDynamicSharedMemorySize, (int)smem);

    ode_kernel<<<256, NT, smem>>>(ts, y0, latent, length, dts, dcs,
                                  W1, b1, W2, b2, W3, b3, out);
}